// round 12
// baseline (speedup 1.0000x reference)
#include <cuda_runtime.h>
#include <math.h>

#define STEPS 2048
#define BATCH 512
#define NBLK  128
#define THREADS 512

typedef unsigned long long u64;

__device__ float g_baseflow[BATCH];

// ---------------------------------------------------------------------------
__device__ __forceinline__ u64 pack2(float lo, float hi) {
    u64 r; asm("mov.b64 %0, {%1, %2};" : "=l"(r) : "f"(lo), "f"(hi)); return r;
}
__device__ __forceinline__ void fma2(u64& acc, u64 a, u64 b) {
    asm("fma.rn.f32x2 %0, %1, %2, %0;" : "+l"(acc) : "l"(a), "l"(b));
}
__device__ __forceinline__ u64 add2(u64 a, u64 b) {
    u64 r; asm("add.rn.f32x2 %0, %1, %2;" : "=l"(r) : "l"(a), "l"(b)); return r;
}
__device__ __forceinline__ float fast_sigmoid(float v) {
    return __fdividef(1.0f, 1.0f + __expf(-v));
}

// ---------------------------------------------------------------------------
// Kernel 1: per-batch-element 25th percentile of flow (bitonic sort)
// ---------------------------------------------------------------------------
__global__ void baseflow_kernel(const float* __restrict__ hyd) {
    __shared__ float v[STEPS];
    const int b = blockIdx.x;
    const int tid = threadIdx.x;
    for (int t = tid; t < STEPS; t += blockDim.x)
        v[t] = hyd[(t * BATCH + b) * 17];
    __syncthreads();
    for (int k = 2; k <= STEPS; k <<= 1) {
        for (int j = k >> 1; j > 0; j >>= 1) {
            for (int i = tid; i < STEPS; i += blockDim.x) {
                int l = i ^ j;
                if (l > i) {
                    float a = v[i], c = v[l];
                    bool up = ((i & k) == 0);
                    if ((a > c) == up) { v[i] = c; v[l] = a; }
                }
            }
            __syncthreads();
        }
    }
    if (tid == 0)
        g_baseflow[b] = 0.25f * v[511] + 0.75f * v[512];   // pos = 511.75
}

// ---------------------------------------------------------------------------
// SMEM (~70 KB, dynamic)
// ---------------------------------------------------------------------------
struct __align__(16) Smem {
    float wct[128 * 96];     // 48KB layer2 weights [k][j] (j<89 valid, rest 0)
    float part1[4 * 512];    // [q][j][s] flat
    float part2[4 * 384];    // [q][j][s] flat, j padded to 96
    float hA[512];           // [j][s]
    float hB[512];           // [j][s]
    float l0p[512];          // [j][s]
    float xin[64];           // [i][s]
    float outg[4 * 80];      // [s][col]
    float lgt[4 * 16];       // [s][j] logits
    float st[32];            // [s][k]
    float bflow_s[4];
};

// ---------------------------------------------------------------------------
// 512 threads = 16 warps, 4 samples, one CTA/SM, one wave.
// j = tid&127 owns unit j; q = tid>>7 owns k-slice [32q, 32q+32).
// Stages (6 barriers) — same schedule as R11; S3 weights now in SMEM and
// both fat matvecs use 4 independent accumulator chains.
// ---------------------------------------------------------------------------
__global__ void __launch_bounds__(THREADS, 1)
hyd_kernel(const float* __restrict__ hyd,
           const float* __restrict__ W0, const float* __restrict__ b0,
           const float* __restrict__ W1, const float* __restrict__ b1,
           const float* __restrict__ Wi, const float* __restrict__ bi,
           const float* __restrict__ Wo, const float* __restrict__ bo,
           float* __restrict__ out)
{
    extern __shared__ char raw[];
    Smem& S = *(Smem*)raw;
    const int tid  = threadIdx.x;
    const int j    = tid & 127;
    const int q    = tid >> 7;
    const int lane = tid & 31;
    const int warp = tid >> 5;
    const int blk  = blockIdx.x;

    // ---- register-resident layer1 weights ----
    float w1r[32];
    float b1R = (q == 0) ? b1[j] : 0.f;
    #pragma unroll
    for (int k = 0; k < 32; k++) w1r[k] = W1[j * 128 + q * 32 + k];
    float bcR = 0.f;
    if (j < 9)        { if (q == 0) bcR = bi[j]; }
    else if (j < 89)  { if (q == 0) bcR = bo[j - 9]; }

    // l0x role (warps 3/7/11/15): unit q*32+lane
    float w0tR[16], b0R = 0.f;
    if ((warp & 3) == 3) {
        int jj = q * 32 + lane;
        b0R = b0[jj];
        #pragma unroll
        for (int i = 0; i < 16; i++) w0tR[i] = W0[jj * 24 + i];
    }
    // hA-finish role (all): unit tid>>2
    float w0spR[8];
    {
        int jj = tid >> 2;
        #pragma unroll
        for (int k = 0; k < 8; k++) w0spR[k] = 0.01f * W0[jj * 24 + 16 + k];
    }

    // ---- SMEM weight init: wct[k][j] ----
    for (int idx = tid; idx < 128 * 96; idx += THREADS) {
        int k = idx / 96, jj = idx - (idx / 96) * 96;
        float v = 0.f;
        if (jj < 9)       v = Wi[jj * 128 + k];
        else if (jj < 89) v = Wo[(jj - 9) * 128 + k];
        S.wct[idx] = v;
    }

    // per-warp roles
    const int bsample = blk * 4 + warp;          // warps 0-3: epilogue sample
    const int xsample = blk * 4 + (warp - 8);    // warps 8-11: x prefetch
    float rain_cur = 0.f, rain_next = 0.f, xreg = 0.f;

    if (warp < 4 && lane == 0) rain_cur = hyd[bsample * 17 + 1];
    if (warp < 4 && lane < 4)  S.bflow_s[lane] = g_baseflow[blk * 4 + lane];
    if (warp >= 8 && warp < 12 && lane < 16)
        S.xin[lane * 4 + (warp - 8)] = hyd[xsample * 17 + 1 + lane];
    if (tid < 32) S.st[tid] = ((tid & 7) == 1) ? 1.0f : 0.0f;
    __syncthreads();

    // ---- bootstrap: l0p(0) ----
    if ((warp & 3) == 3) {
        int jj = q * 32 + lane;
        u64 a01 = pack2(b0R, b0R), a23 = a01;
        #pragma unroll
        for (int i = 0; i < 16; i++) {
            ulonglong2 h = *(const ulonglong2*)&S.xin[i * 4];
            u64 wd = pack2(w0tR[i], w0tR[i]);
            fma2(a01, h.x, wd); fma2(a23, h.y, wd);
        }
        ulonglong2 pv; pv.x = a01; pv.y = a23;
        *(ulonglong2*)&S.l0p[jj * 4] = pv;
    }
    __syncthreads();
    // ---- bootstrap: hA(0) ----
    {
        int s = tid & 3;
        float4 s0 = *(const float4*)&S.st[s * 8];
        float4 s1 = *(const float4*)&S.st[s * 8 + 4];
        float v = S.l0p[tid];
        v = fmaf(w0spR[0], s0.x, v); v = fmaf(w0spR[1], s0.y, v);
        v = fmaf(w0spR[2], s0.z, v); v = fmaf(w0spR[3], s0.w, v);
        v = fmaf(w0spR[4], s1.x, v); v = fmaf(w0spR[5], s1.y, v);
        v = fmaf(w0spR[6], s1.z, v); v = fmaf(w0spR[7], s1.w, v);
        S.hA[tid] = fmaxf(v, 0.f);
    }
    __syncthreads();

    // persistent stores in lane 0 of warps 0-3
    float sv[8];
    #pragma unroll
    for (int k = 0; k < 8; k++) sv[k] = (k == 1) ? 1.0f : 0.0f;

    for (int t = 0; t < STEPS; t++) {
        // ======== S1: layer1 partials (+ prefetch), 4 acc chains ========
        if (t + 1 < STEPS) {
            if (warp < 4 && lane == 0)
                rain_next = hyd[((t + 1) * BATCH + bsample) * 17 + 1];
            if (warp >= 8 && warp < 12 && lane < 16)
                xreg = hyd[((t + 1) * BATCH + xsample) * 17 + 1 + lane];
        }
        {
            u64 a01 = pack2(b1R, b1R), a23 = a01;
            u64 c01 = pack2(0.f, 0.f), c23 = c01;
            const float* hp = &S.hA[q * 128];
            #pragma unroll
            for (int k = 0; k < 16; k++) {
                ulonglong2 ha = *(const ulonglong2*)&hp[k * 4];
                ulonglong2 hb = *(const ulonglong2*)&hp[(k + 16) * 4];
                u64 wa = pack2(w1r[k], w1r[k]);
                u64 wb = pack2(w1r[k + 16], w1r[k + 16]);
                fma2(a01, ha.x, wa); fma2(a23, ha.y, wa);
                fma2(c01, hb.x, wb); fma2(c23, hb.y, wb);
            }
            ulonglong2 pv; pv.x = add2(a01, c01); pv.y = add2(a23, c23);
            *(ulonglong2*)&S.part1[q * 512 + j * 4] = pv;
        }
        __syncthreads();

        // ======== S2: combine1 -> hB ; stage xin ========
        {
            float v = S.part1[tid]        + S.part1[512 + tid]
                    + S.part1[1024 + tid] + S.part1[1536 + tid];
            S.hB[tid] = fmaxf(v, 0.f);
        }
        if (warp >= 8 && warp < 12 && lane < 16)
            S.xin[lane * 4 + (warp - 8)] = xreg;
        __syncthreads();

        // ======== S3: layer2 partials (SMEM weights) || l0x(t+1) ========
        if ((warp & 3) == 3) {
            int jj = q * 32 + lane;
            u64 a01 = pack2(b0R, b0R), a23 = a01;
            #pragma unroll
            for (int i = 0; i < 16; i++) {
                ulonglong2 h = *(const ulonglong2*)&S.xin[i * 4];
                u64 wd = pack2(w0tR[i], w0tR[i]);
                fma2(a01, h.x, wd); fma2(a23, h.y, wd);
            }
            ulonglong2 pv; pv.x = a01; pv.y = a23;
            *(ulonglong2*)&S.l0p[jj * 4] = pv;
        } else {
            // j < 96 here (warps 3 mod 4 excluded). weights from SMEM, 4 chains
            u64 a01 = pack2(bcR, bcR), a23 = a01;
            u64 c01 = pack2(0.f, 0.f), c23 = c01;
            const float* hp = &S.hB[q * 128];
            const float* wp = &S.wct[q * 32 * 96 + j];
            #pragma unroll
            for (int k = 0; k < 16; k++) {
                float wa = wp[k * 96];
                float wb = wp[(k + 16) * 96];
                ulonglong2 ha = *(const ulonglong2*)&hp[k * 4];
                ulonglong2 hb = *(const ulonglong2*)&hp[(k + 16) * 4];
                u64 wda = pack2(wa, wa), wdb = pack2(wb, wb);
                fma2(a01, ha.x, wda); fma2(a23, ha.y, wda);
                fma2(c01, hb.x, wdb); fma2(c23, hb.y, wdb);
            }
            ulonglong2 pv; pv.x = add2(a01, c01); pv.y = add2(a23, c23);
            *(ulonglong2*)&S.part2[q * 384 + j * 4] = pv;
        }
        __syncthreads();

        // ======== S4: combine2 + sigmoid / logits (356 thr) ========
        if (tid < 356) {
            int jj = tid >> 2, s = tid & 3;
            float v = S.part2[tid]        + S.part2[384 + tid]
                    + S.part2[768 + tid]  + S.part2[1152 + tid];
            if (jj < 9) S.lgt[s * 16 + jj] = v;
            else        S.outg[s * 80 + jj - 9] = fast_sigmoid(v);
        }
        __syncthreads();

        // ======== S5: epilogue (warps 0-3, lane 0 scalar) ========
        if (warp < 4 && lane == 0) {
            const int s = warp;
            float4 la = *(const float4*)&S.lgt[s * 16];
            float4 lb = *(const float4*)&S.lgt[s * 16 + 4];
            float  l8 = S.lgt[s * 16 + 8];
            float m01 = fmaxf(la.x, la.y), m23 = fmaxf(la.z, la.w);
            float m45 = fmaxf(lb.x, lb.y), m67 = fmaxf(lb.z, lb.w);
            float m = fmaxf(fmaxf(fmaxf(m01, m23), fmaxf(m45, m67)), l8);
            float e0 = __expf(la.x - m), e1 = __expf(la.y - m);
            float e2 = __expf(la.z - m), e3 = __expf(la.w - m);
            float e4 = __expf(lb.x - m), e5 = __expf(lb.y - m);
            float e6 = __expf(lb.z - m), e7 = __expf(lb.w - m);
            float e8 = __expf(l8 - m);
            float ssum = (((e0 + e1) + (e2 + e3)) + ((e4 + e5) + (e6 + e7))) + e8;
            float r2 = __fdividef(rain_cur, ssum);
            sv[0] += e1 * r2; sv[1] += e2 * r2; sv[2] += e3 * r2; sv[3] += e4 * r2;
            sv[4] += e5 * r2; sv[5] += e6 * r2; sv[6] += e7 * r2; sv[7] += e8 * r2;

            const float* bb = &S.outg[s * 80];
            #pragma unroll
            for (int d = 0; d < 8; d++) {
                float4 bv0 = *(const float4*)&bb[d * 8];
                float4 bv1 = *(const float4*)&bb[d * 8 + 4];
                float fb0 = bv0.x * sv[0], fb1 = bv0.y * sv[1];
                float fb2 = bv0.z * sv[2], fb3 = bv0.w * sv[3];
                float fb4 = bv1.x * sv[4], fb5 = bv1.y * sv[5];
                float fb6 = bv1.z * sv[6], fb7 = bv1.w * sv[7];
                float fsum = ((fb0 + fb1) + (fb2 + fb3))
                           + ((fb4 + fb5) + (fb6 + fb7));
                sv[0] -= fb0; sv[1] -= fb1; sv[2] -= fb2; sv[3] -= fb3;
                sv[4] -= fb4; sv[5] -= fb5; sv[6] -= fb6; sv[7] -= fb7;
                sv[d] += fsum;
            }
            {   // escape
                float4 ea = *(const float4*)&bb[64];
                float4 eb = *(const float4*)&bb[68];
                sv[0] -= ea.x * sv[0]; sv[1] -= ea.y * sv[1];
                sv[2] -= ea.z * sv[2]; sv[3] -= ea.w * sv[3];
                sv[4] -= eb.x * sv[4]; sv[5] -= eb.y * sv[5];
                sv[6] -= eb.z * sv[6]; sv[7] -= eb.w * sv[7];
            }
            {   // flow distn
                float4 f0 = *(const float4*)&bb[72];
                float4 f1 = *(const float4*)&bb[76];
                float fd0 = f0.x * sv[0], fd1 = f0.y * sv[1];
                float fd2 = f0.z * sv[2], fd3 = f0.w * sv[3];
                float fd4 = f1.x * sv[4], fd5 = f1.y * sv[5];
                float fd6 = f1.z * sv[6], fd7 = f1.w * sv[7];
                float flow = ((fd0 + fd1) + (fd2 + fd3))
                           + ((fd4 + fd5) + (fd6 + fd7));
                sv[0] -= fd0; sv[1] -= fd1; sv[2] -= fd2; sv[3] -= fd3;
                sv[4] -= fd4; sv[5] -= fd5; sv[6] -= fd6; sv[7] -= fd7;
                out[t * BATCH + bsample] = flow;
                if (t == 0)
                    sv[2] = S.bflow_s[s] / fmaxf(f0.z, 1e-5f);   // b_flow[SLOW]
            }
            *(float4*)&S.st[s * 8]     = make_float4(sv[0], sv[1], sv[2], sv[3]);
            *(float4*)&S.st[s * 8 + 4] = make_float4(sv[4], sv[5], sv[6], sv[7]);
            rain_cur = rain_next;
        }
        __syncthreads();

        // ======== S6: hA(t+1) finish (512 thr) ========
        {
            int s = tid & 3;
            float4 s0 = *(const float4*)&S.st[s * 8];
            float4 s1 = *(const float4*)&S.st[s * 8 + 4];
            float v = S.l0p[tid];
            v = fmaf(w0spR[0], s0.x, v); v = fmaf(w0spR[1], s0.y, v);
            v = fmaf(w0spR[2], s0.z, v); v = fmaf(w0spR[3], s0.w, v);
            v = fmaf(w0spR[4], s1.x, v); v = fmaf(w0spR[5], s1.y, v);
            v = fmaf(w0spR[6], s1.z, v); v = fmaf(w0spR[7], s1.w, v);
            S.hA[tid] = fmaxf(v, 0.f);
        }
        __syncthreads();
    }
}

// ---------------------------------------------------------------------------
// Harness entry.  Inputs: hyd_input, W0, b0, W1, b1, W_in, b_in, W_out, b_out
// ---------------------------------------------------------------------------
extern "C" void kernel_launch(void* const* d_in, const int* in_sizes, int n_in,
                              void* d_out, int out_size) {
    const float* hyd = (const float*)d_in[0];
    const float* W0  = (const float*)d_in[1];
    const float* b0  = (const float*)d_in[2];
    const float* W1  = (const float*)d_in[3];
    const float* b1  = (const float*)d_in[4];
    const float* Wi  = (const float*)d_in[5];
    const float* bi  = (const float*)d_in[6];
    const float* Wo  = (const float*)d_in[7];
    const float* bo  = (const float*)d_in[8];
    float* out = (float*)d_out;

    cudaFuncSetAttribute(hyd_kernel,
                         cudaFuncAttributeMaxDynamicSharedMemorySize,
                         (int)sizeof(Smem));

    baseflow_kernel<<<BATCH, 1024>>>(hyd);
    hyd_kernel<<<NBLK, THREADS, sizeof(Smem)>>>(hyd, W0, b0, W1, b1, Wi, bi, Wo, bo, out);
}

// round 14
// speedup vs baseline: 1.6646x; 1.6646x over previous
#include <cuda_runtime.h>
#include <math.h>

#define STEPS 2048
#define BATCH 512
#define NBLK  128
#define THREADS 512

typedef unsigned long long u64;

__device__ float g_baseflow[BATCH];

// ---------------------------------------------------------------------------
__device__ __forceinline__ u64 pack2(float lo, float hi) {
    u64 r; asm("mov.b64 %0, {%1, %2};" : "=l"(r) : "f"(lo), "f"(hi)); return r;
}
__device__ __forceinline__ void unpack2(u64 v, float& lo, float& hi) {
    asm("mov.b64 {%0, %1}, %2;" : "=f"(lo), "=f"(hi) : "l"(v));
}
__device__ __forceinline__ void fma2(u64& acc, u64 a, u64 b) {
    asm("fma.rn.f32x2 %0, %1, %2, %0;" : "+l"(acc) : "l"(a), "l"(b));
}
__device__ __forceinline__ float fast_sigmoid(float v) {
    return __fdividef(1.0f, 1.0f + __expf(-v));
}

// ---------------------------------------------------------------------------
// Kernel 1: per-batch-element 25th percentile of flow (bitonic sort)
// ---------------------------------------------------------------------------
__global__ void baseflow_kernel(const float* __restrict__ hyd) {
    __shared__ float v[STEPS];
    const int b = blockIdx.x;
    const int tid = threadIdx.x;
    for (int t = tid; t < STEPS; t += blockDim.x)
        v[t] = hyd[(t * BATCH + b) * 17];
    __syncthreads();
    for (int k = 2; k <= STEPS; k <<= 1) {
        for (int j = k >> 1; j > 0; j >>= 1) {
            for (int i = tid; i < STEPS; i += blockDim.x) {
                int l = i ^ j;
                if (l > i) {
                    float a = v[i], c = v[l];
                    bool up = ((i & k) == 0);
                    if ((a > c) == up) { v[i] = c; v[l] = a; }
                }
            }
            __syncthreads();
        }
    }
    if (tid == 0)
        g_baseflow[b] = 0.25f * v[511] + 0.75f * v[512];   // pos = 511.75
}

// ---------------------------------------------------------------------------
// SMEM (~32 KB, static)
// ---------------------------------------------------------------------------
struct __align__(16) Smem {
    float part1[4 * 512];    // [q][s][j]: q*512 + s*128 + j
    float part2[4 * 384];    // [q][s][j96]: q*384 + s*96 + j
    float hA[512];           // [s][k]: s*128 + k
    float hB[512];           // [s][k]
    float l0p[512];          // [s][j]
    float xin[64];           // [i][s]
    float outg[4 * 80];      // [s][col]
    float lgt[4 * 16];       // [s][j]
    float st[32];            // [s][k]
    float bflow_s[4];
};

// ---------------------------------------------------------------------------
// 512 threads = 16 warps, 4 samples, one CTA/SM, one wave.
// j = tid&127 owns unit j; q = tid>>7 owns k-slice [32q, 32q+32).
// f32x2 packs K-PAIRS: acc[s] = (sum over even k, sum over odd k); weights
// are pre-packed loop-invariant u64 (w_2k, w_2k+1) -> zero in-loop MOVs.
// Bias is added PER SAMPLE at accumulator collapse (q==0 threads only).
// Activations stored [s][k] so h-pairs are contiguous.
// Stages (6 barriers): same schedule as R11.
// ---------------------------------------------------------------------------
__global__ void __launch_bounds__(THREADS, 1)
hyd_kernel(const float* __restrict__ hyd,
           const float* __restrict__ W0, const float* __restrict__ b0,
           const float* __restrict__ W1, const float* __restrict__ b1,
           const float* __restrict__ Wi, const float* __restrict__ bi,
           const float* __restrict__ Wo, const float* __restrict__ bo,
           float* __restrict__ out)
{
    __shared__ Smem S;
    const int tid  = threadIdx.x;
    const int j    = tid & 127;
    const int q    = tid >> 7;
    const int lane = tid & 31;
    const int warp = tid >> 5;
    const int blk  = blockIdx.x;

    // ---- register-resident packed weight pairs ----
    u64 w1d[16], wcd[16];
    float b1R = (q == 0) ? b1[j] : 0.f;
    float bcR = 0.f;
    #pragma unroll
    for (int k = 0; k < 16; k++)
        w1d[k] = pack2(W1[j * 128 + q * 32 + 2 * k], W1[j * 128 + q * 32 + 2 * k + 1]);
    if (j < 9) {
        if (q == 0) bcR = bi[j];
        #pragma unroll
        for (int k = 0; k < 16; k++)
            wcd[k] = pack2(Wi[j * 128 + q * 32 + 2 * k], Wi[j * 128 + q * 32 + 2 * k + 1]);
    } else if (j < 89) {
        if (q == 0) bcR = bo[j - 9];
        #pragma unroll
        for (int k = 0; k < 16; k++)
            wcd[k] = pack2(Wo[(j - 9) * 128 + q * 32 + 2 * k], Wo[(j - 9) * 128 + q * 32 + 2 * k + 1]);
    } else {
        #pragma unroll
        for (int k = 0; k < 16; k++) wcd[k] = 0ull;
    }
    // l0x role (warps 3/7/11/15): unit q*32+lane
    float w0tR[16], b0R = 0.f;
    if ((warp & 3) == 3) {
        int jj = q * 32 + lane;
        b0R = b0[jj];
        #pragma unroll
        for (int i = 0; i < 16; i++) w0tR[i] = W0[jj * 24 + i];
    }
    // hA-finish role (all): unit j = tid&127, sample s = tid>>7
    float w0spR[8];
    #pragma unroll
    for (int k = 0; k < 8; k++) w0spR[k] = 0.01f * W0[j * 24 + 16 + k];

    // per-warp roles
    const int bsample = blk * 4 + warp;          // warps 0-3: epilogue sample
    const int xsample = blk * 4 + (warp - 8);    // warps 8-11: x prefetch
    float rain_cur = 0.f, rain_next = 0.f, xreg = 0.f;

    if (warp < 4 && lane == 0) rain_cur = hyd[bsample * 17 + 1];
    if (warp < 4 && lane < 4)  S.bflow_s[lane] = g_baseflow[blk * 4 + lane];
    if (warp >= 8 && warp < 12 && lane < 16)
        S.xin[lane * 4 + (warp - 8)] = hyd[xsample * 17 + 1 + lane];
    if (tid < 32) S.st[tid] = ((tid & 7) == 1) ? 1.0f : 0.0f;
    __syncthreads();

    // ---- bootstrap: l0p(0) ([s][j] layout) ----
    if ((warp & 3) == 3) {
        int jj = q * 32 + lane;
        u64 a01 = pack2(b0R, b0R), a23 = a01;
        #pragma unroll
        for (int i = 0; i < 16; i++) {
            ulonglong2 h = *(const ulonglong2*)&S.xin[i * 4];
            u64 wd = pack2(w0tR[i], w0tR[i]);
            fma2(a01, h.x, wd); fma2(a23, h.y, wd);
        }
        float f0, f1, f2, f3;
        unpack2(a01, f0, f1); unpack2(a23, f2, f3);
        S.l0p[0 * 128 + jj] = f0; S.l0p[1 * 128 + jj] = f1;
        S.l0p[2 * 128 + jj] = f2; S.l0p[3 * 128 + jj] = f3;
    }
    __syncthreads();
    // ---- bootstrap: hA(0) ([s][k] layout) ----
    {
        int s = tid >> 7;
        float4 s0 = *(const float4*)&S.st[s * 8];
        float4 s1 = *(const float4*)&S.st[s * 8 + 4];
        float v = S.l0p[s * 128 + j];
        v = fmaf(w0spR[0], s0.x, v); v = fmaf(w0spR[1], s0.y, v);
        v = fmaf(w0spR[2], s0.z, v); v = fmaf(w0spR[3], s0.w, v);
        v = fmaf(w0spR[4], s1.x, v); v = fmaf(w0spR[5], s1.y, v);
        v = fmaf(w0spR[6], s1.z, v); v = fmaf(w0spR[7], s1.w, v);
        S.hA[s * 128 + j] = fmaxf(v, 0.f);
    }
    __syncthreads();

    // persistent stores in lane 0 of warps 0-3
    float sv[8];
    #pragma unroll
    for (int k = 0; k < 8; k++) sv[k] = (k == 1) ? 1.0f : 0.0f;

    for (int t = 0; t < STEPS; t++) {
        // ======== S1: layer1 partials (+ prefetch) ========
        if (t + 1 < STEPS) {
            if (warp < 4 && lane == 0)
                rain_next = hyd[((t + 1) * BATCH + bsample) * 17 + 1];
            if (warp >= 8 && warp < 12 && lane < 16)
                xreg = hyd[((t + 1) * BATCH + xsample) * 17 + 1 + lane];
        }
        {
            u64 acc0 = 0ull, acc1 = 0ull, acc2 = 0ull, acc3 = 0ull;
            const float* hb = &S.hA[q * 32];
            #pragma unroll
            for (int kk = 0; kk < 8; kk++) {
                u64 wa = w1d[2 * kk], wb = w1d[2 * kk + 1];
                ulonglong2 h0 = *(const ulonglong2*)&hb[0 * 128 + kk * 4];
                ulonglong2 h1 = *(const ulonglong2*)&hb[1 * 128 + kk * 4];
                ulonglong2 h2 = *(const ulonglong2*)&hb[2 * 128 + kk * 4];
                ulonglong2 h3 = *(const ulonglong2*)&hb[3 * 128 + kk * 4];
                fma2(acc0, h0.x, wa); fma2(acc0, h0.y, wb);
                fma2(acc1, h1.x, wa); fma2(acc1, h1.y, wb);
                fma2(acc2, h2.x, wa); fma2(acc2, h2.y, wb);
                fma2(acc3, h3.x, wa); fma2(acc3, h3.y, wb);
            }
            float lo, hi;
            unpack2(acc0, lo, hi); S.part1[q * 512 + 0 * 128 + j] = b1R + (lo + hi);
            unpack2(acc1, lo, hi); S.part1[q * 512 + 1 * 128 + j] = b1R + (lo + hi);
            unpack2(acc2, lo, hi); S.part1[q * 512 + 2 * 128 + j] = b1R + (lo + hi);
            unpack2(acc3, lo, hi); S.part1[q * 512 + 3 * 128 + j] = b1R + (lo + hi);
        }
        __syncthreads();

        // ======== S2: combine1 -> hB ([s][k], flat coalesced) ; stage xin ==
        {
            float v = S.part1[tid]        + S.part1[512 + tid]
                    + S.part1[1024 + tid] + S.part1[1536 + tid];
            S.hB[tid] = fmaxf(v, 0.f);
        }
        if (warp >= 8 && warp < 12 && lane < 16)
            S.xin[lane * 4 + (warp - 8)] = xreg;
        __syncthreads();

        // ======== S3: layer2 partials || l0x(t+1) ========
        if ((warp & 3) == 3) {
            int jj = q * 32 + lane;
            u64 a01 = pack2(b0R, b0R), a23 = a01;
            #pragma unroll
            for (int i = 0; i < 16; i++) {
                ulonglong2 h = *(const ulonglong2*)&S.xin[i * 4];
                u64 wd = pack2(w0tR[i], w0tR[i]);
                fma2(a01, h.x, wd); fma2(a23, h.y, wd);
            }
            float f0, f1, f2, f3;
            unpack2(a01, f0, f1); unpack2(a23, f2, f3);
            S.l0p[0 * 128 + jj] = f0; S.l0p[1 * 128 + jj] = f1;
            S.l0p[2 * 128 + jj] = f2; S.l0p[3 * 128 + jj] = f3;
        } else {
            u64 acc0 = 0ull, acc1 = 0ull, acc2 = 0ull, acc3 = 0ull;
            const float* hb = &S.hB[q * 32];
            #pragma unroll
            for (int kk = 0; kk < 8; kk++) {
                u64 wa = wcd[2 * kk], wb = wcd[2 * kk + 1];
                ulonglong2 h0 = *(const ulonglong2*)&hb[0 * 128 + kk * 4];
                ulonglong2 h1 = *(const ulonglong2*)&hb[1 * 128 + kk * 4];
                ulonglong2 h2 = *(const ulonglong2*)&hb[2 * 128 + kk * 4];
                ulonglong2 h3 = *(const ulonglong2*)&hb[3 * 128 + kk * 4];
                fma2(acc0, h0.x, wa); fma2(acc0, h0.y, wb);
                fma2(acc1, h1.x, wa); fma2(acc1, h1.y, wb);
                fma2(acc2, h2.x, wa); fma2(acc2, h2.y, wb);
                fma2(acc3, h3.x, wa); fma2(acc3, h3.y, wb);
            }
            float lo, hi;
            unpack2(acc0, lo, hi); S.part2[q * 384 + 0 * 96 + j] = bcR + (lo + hi);
            unpack2(acc1, lo, hi); S.part2[q * 384 + 1 * 96 + j] = bcR + (lo + hi);
            unpack2(acc2, lo, hi); S.part2[q * 384 + 2 * 96 + j] = bcR + (lo + hi);
            unpack2(acc3, lo, hi); S.part2[q * 384 + 3 * 96 + j] = bcR + (lo + hi);
        }
        __syncthreads();

        // ======== S4: combine2 + sigmoid / logits (384 thr, coalesced) ====
        if (tid < 384) {
            int s  = tid / 96;
            int jj = tid - s * 96;
            float v = S.part2[tid]        + S.part2[384 + tid]
                    + S.part2[768 + tid]  + S.part2[1152 + tid];
            if (jj < 9)       S.lgt[s * 16 + jj] = v;
            else if (jj < 89) S.outg[s * 80 + jj - 9] = fast_sigmoid(v);
        }
        __syncthreads();

        // ======== S5: epilogue (warps 0-3, lane 0 scalar) ========
        if (warp < 4 && lane == 0) {
            const int s = warp;
            float4 la = *(const float4*)&S.lgt[s * 16];
            float4 lb = *(const float4*)&S.lgt[s * 16 + 4];
            float  l8 = S.lgt[s * 16 + 8];
            float m01 = fmaxf(la.x, la.y), m23 = fmaxf(la.z, la.w);
            float m45 = fmaxf(lb.x, lb.y), m67 = fmaxf(lb.z, lb.w);
            float m = fmaxf(fmaxf(fmaxf(m01, m23), fmaxf(m45, m67)), l8);
            float e0 = __expf(la.x - m), e1 = __expf(la.y - m);
            float e2 = __expf(la.z - m), e3 = __expf(la.w - m);
            float e4 = __expf(lb.x - m), e5 = __expf(lb.y - m);
            float e6 = __expf(lb.z - m), e7 = __expf(lb.w - m);
            float e8 = __expf(l8 - m);
            float ssum = (((e0 + e1) + (e2 + e3)) + ((e4 + e5) + (e6 + e7))) + e8;
            float r2 = __fdividef(rain_cur, ssum);
            sv[0] += e1 * r2; sv[1] += e2 * r2; sv[2] += e3 * r2; sv[3] += e4 * r2;
            sv[4] += e5 * r2; sv[5] += e6 * r2; sv[6] += e7 * r2; sv[7] += e8 * r2;

            const float* bb = &S.outg[s * 80];
            #pragma unroll
            for (int d = 0; d < 8; d++) {
                float4 bv0 = *(const float4*)&bb[d * 8];
                float4 bv1 = *(const float4*)&bb[d * 8 + 4];
                float fb0 = bv0.x * sv[0], fb1 = bv0.y * sv[1];
                float fb2 = bv0.z * sv[2], fb3 = bv0.w * sv[3];
                float fb4 = bv1.x * sv[4], fb5 = bv1.y * sv[5];
                float fb6 = bv1.z * sv[6], fb7 = bv1.w * sv[7];
                float fsum = ((fb0 + fb1) + (fb2 + fb3))
                           + ((fb4 + fb5) + (fb6 + fb7));
                sv[0] -= fb0; sv[1] -= fb1; sv[2] -= fb2; sv[3] -= fb3;
                sv[4] -= fb4; sv[5] -= fb5; sv[6] -= fb6; sv[7] -= fb7;
                sv[d] += fsum;
            }
            {   // escape
                float4 ea = *(const float4*)&bb[64];
                float4 eb = *(const float4*)&bb[68];
                sv[0] -= ea.x * sv[0]; sv[1] -= ea.y * sv[1];
                sv[2] -= ea.z * sv[2]; sv[3] -= ea.w * sv[3];
                sv[4] -= eb.x * sv[4]; sv[5] -= eb.y * sv[5];
                sv[6] -= eb.z * sv[6]; sv[7] -= eb.w * sv[7];
            }
            {   // flow distn
                float4 f0 = *(const float4*)&bb[72];
                float4 f1 = *(const float4*)&bb[76];
                float fd0 = f0.x * sv[0], fd1 = f0.y * sv[1];
                float fd2 = f0.z * sv[2], fd3 = f0.w * sv[3];
                float fd4 = f1.x * sv[4], fd5 = f1.y * sv[5];
                float fd6 = f1.z * sv[6], fd7 = f1.w * sv[7];
                float flow = ((fd0 + fd1) + (fd2 + fd3))
                           + ((fd4 + fd5) + (fd6 + fd7));
                sv[0] -= fd0; sv[1] -= fd1; sv[2] -= fd2; sv[3] -= fd3;
                sv[4] -= fd4; sv[5] -= fd5; sv[6] -= fd6; sv[7] -= fd7;
                out[t * BATCH + bsample] = flow;
                if (t == 0)
                    sv[2] = S.bflow_s[s] / fmaxf(f0.z, 1e-5f);   // b_flow[SLOW]
            }
            *(float4*)&S.st[s * 8]     = make_float4(sv[0], sv[1], sv[2], sv[3]);
            *(float4*)&S.st[s * 8 + 4] = make_float4(sv[4], sv[5], sv[6], sv[7]);
            rain_cur = rain_next;
        }
        __syncthreads();

        // ======== S6: hA(t+1) finish (512 thr, [s][k] layout) ========
        {
            int s = tid >> 7;
            float4 s0 = *(const float4*)&S.st[s * 8];
            float4 s1 = *(const float4*)&S.st[s * 8 + 4];
            float v = S.l0p[s * 128 + j];
            v = fmaf(w0spR[0], s0.x, v); v = fmaf(w0spR[1], s0.y, v);
            v = fmaf(w0spR[2], s0.z, v); v = fmaf(w0spR[3], s0.w, v);
            v = fmaf(w0spR[4], s1.x, v); v = fmaf(w0spR[5], s1.y, v);
            v = fmaf(w0spR[6], s1.z, v); v = fmaf(w0spR[7], s1.w, v);
            S.hA[s * 128 + j] = fmaxf(v, 0.f);
        }
        __syncthreads();
    }
}

// ---------------------------------------------------------------------------
// Harness entry.  Inputs: hyd_input, W0, b0, W1, b1, W_in, b_in, W_out, b_out
// ---------------------------------------------------------------------------
extern "C" void kernel_launch(void* const* d_in, const int* in_sizes, int n_in,
                              void* d_out, int out_size) {
    const float* hyd = (const float*)d_in[0];
    const float* W0  = (const float*)d_in[1];
    const float* b0  = (const float*)d_in[2];
    const float* W1  = (const float*)d_in[3];
    const float* b1  = (const float*)d_in[4];
    const float* Wi  = (const float*)d_in[5];
    const float* bi  = (const float*)d_in[6];
    const float* Wo  = (const float*)d_in[7];
    const float* bo  = (const float*)d_in[8];
    float* out = (float*)d_out;

    baseflow_kernel<<<BATCH, 1024>>>(hyd);
    hyd_kernel<<<NBLK, THREADS>>>(hyd, W0, b0, W1, b1, Wi, bi, Wo, bo, out);
}

// round 15
// speedup vs baseline: 1.8176x; 1.0919x over previous
#include <cuda_runtime.h>
#include <math.h>

#define STEPS 2048
#define BATCH 512
#define NBLK  128
#define THREADS 512

typedef unsigned long long u64;

__device__ float g_baseflow[BATCH];

// ---------------------------------------------------------------------------
__device__ __forceinline__ u64 pack2(float lo, float hi) {
    u64 r; asm("mov.b64 %0, {%1, %2};" : "=l"(r) : "f"(lo), "f"(hi)); return r;
}
__device__ __forceinline__ void fma2(u64& acc, u64 a, u64 b) {
    asm("fma.rn.f32x2 %0, %1, %2, %0;" : "+l"(acc) : "l"(a), "l"(b));
}
__device__ __forceinline__ float fast_sigmoid(float v) {
    return __fdividef(1.0f, 1.0f + __expf(-v));
}

// ---------------------------------------------------------------------------
// Kernel 1: per-batch-element 25th percentile of flow (bitonic sort)
// ---------------------------------------------------------------------------
__global__ void baseflow_kernel(const float* __restrict__ hyd) {
    __shared__ float v[STEPS];
    const int b = blockIdx.x;
    const int tid = threadIdx.x;
    for (int t = tid; t < STEPS; t += blockDim.x)
        v[t] = hyd[(t * BATCH + b) * 17];
    __syncthreads();
    for (int k = 2; k <= STEPS; k <<= 1) {
        for (int j = k >> 1; j > 0; j >>= 1) {
            for (int i = tid; i < STEPS; i += blockDim.x) {
                int l = i ^ j;
                if (l > i) {
                    float a = v[i], c = v[l];
                    bool up = ((i & k) == 0);
                    if ((a > c) == up) { v[i] = c; v[l] = a; }
                }
            }
            __syncthreads();
        }
    }
    if (tid == 0)
        g_baseflow[b] = 0.25f * v[511] + 0.75f * v[512];   // pos = 511.75
}

// ---------------------------------------------------------------------------
// SMEM (~32 KB, static)
// ---------------------------------------------------------------------------
struct __align__(16) Smem {
    float part1[4 * 512];    // [q][j][s] flat: q*512 + j*4 + s
    float part2[4 * 384];    // [q][j][s] flat: q*384 + j*4 + s (j padded to 96)
    float hA[512];           // [k][s]
    float hB[512];           // [k][s]
    float l0p[512];          // [j][s]  (layer0 x-part incl b0)
    float xin[64];           // [i][s]
    float outg[4 * 80];      // [s][col] sigmoided gates
    float lgt[4 * 16];       // [s][j] EXP of logits (unnormalized softmax)
    float st[32];            // [s][k] stores broadcast
    float bflow_s[4];
};

// ---------------------------------------------------------------------------
// 512 threads = 16 warps, 4 samples, one CTA/SM, one wave.
// j = tid&127 owns unit j; q = tid>>7 owns k-slice [32q, 32q+32).
// Stages (6 barriers):
//  S1: layer1 partials + rain(t+1) prefetch
//  S2: combine1 -> hB ; stage x(t+1) into xin, then LDG x(t+2) (full-step
//      load-to-use distance: kills the long_scoreboard stall at S2)
//  S3: layer2 partials (j<89) || warps 3/7/11/15: l0x(t+1) -> l0p
//  S4: combine2; gates -> sigmoid, logits -> EXP (spread MUFU)
//  S5: epilogue warps 0-3 lane 0: tree-sum of exps + divide (no MUFU, no max)
//  S6: hA(t+1) = relu(l0p + 0.01*W0s . st)
// ---------------------------------------------------------------------------
__global__ void __launch_bounds__(THREADS, 1)
hyd_kernel(const float* __restrict__ hyd,
           const float* __restrict__ W0, const float* __restrict__ b0,
           const float* __restrict__ W1, const float* __restrict__ b1,
           const float* __restrict__ Wi, const float* __restrict__ bi,
           const float* __restrict__ Wo, const float* __restrict__ bo,
           float* __restrict__ out)
{
    __shared__ Smem S;
    const int tid  = threadIdx.x;
    const int j    = tid & 127;
    const int q    = tid >> 7;
    const int lane = tid & 31;
    const int warp = tid >> 5;
    const int blk  = blockIdx.x;

    // ---- register-resident weights / biases ----
    float w1r[32], wcr[32];
    float b1R = (q == 0) ? b1[j] : 0.f;
    float bcR = 0.f;
    #pragma unroll
    for (int k = 0; k < 32; k++) w1r[k] = W1[j * 128 + q * 32 + k];
    if (j < 9) {
        if (q == 0) bcR = bi[j];
        #pragma unroll
        for (int k = 0; k < 32; k++) wcr[k] = Wi[j * 128 + q * 32 + k];
    } else if (j < 89) {
        if (q == 0) bcR = bo[j - 9];
        #pragma unroll
        for (int k = 0; k < 32; k++) wcr[k] = Wo[(j - 9) * 128 + q * 32 + k];
    } else {
        #pragma unroll
        for (int k = 0; k < 32; k++) wcr[k] = 0.f;
    }
    // l0x role (warps 3/7/11/15): unit q*32+lane
    float w0tR[16], b0R = 0.f;
    if ((warp & 3) == 3) {
        int jj = q * 32 + lane;
        b0R = b0[jj];
        #pragma unroll
        for (int i = 0; i < 16; i++) w0tR[i] = W0[jj * 24 + i];
    }
    // hA-finish role (all): unit tid>>2
    float w0spR[8];
    {
        int jj = tid >> 2;
        #pragma unroll
        for (int k = 0; k < 8; k++) w0spR[k] = 0.01f * W0[jj * 24 + 16 + k];
    }

    // per-warp roles
    const int bsample = blk * 4 + warp;          // warps 0-3: epilogue sample
    const int xsample = blk * 4 + (warp - 8);    // warps 8-11: x prefetch
    float rain_cur = 0.f, rain_next = 0.f, xreg = 0.f;

    if (warp < 4 && lane == 0) rain_cur = hyd[bsample * 17 + 1];
    if (warp < 4 && lane < 4)  S.bflow_s[lane] = g_baseflow[blk * 4 + lane];
    if (warp >= 8 && warp < 12 && lane < 16) {
        S.xin[lane * 4 + (warp - 8)] = hyd[xsample * 17 + 1 + lane];    // x(0)
        xreg = hyd[(1 * BATCH + xsample) * 17 + 1 + lane];              // x(1)
    }
    if (tid < 32) S.st[tid] = ((tid & 7) == 1) ? 1.0f : 0.0f;
    __syncthreads();

    // ---- bootstrap: l0p(0) ----
    if ((warp & 3) == 3) {
        int jj = q * 32 + lane;
        u64 a01 = pack2(b0R, b0R), a23 = a01;
        #pragma unroll
        for (int i = 0; i < 16; i++) {
            ulonglong2 h = *(const ulonglong2*)&S.xin[i * 4];
            u64 wd = pack2(w0tR[i], w0tR[i]);
            fma2(a01, h.x, wd); fma2(a23, h.y, wd);
        }
        ulonglong2 pv; pv.x = a01; pv.y = a23;
        *(ulonglong2*)&S.l0p[jj * 4] = pv;
    }
    __syncthreads();
    // ---- bootstrap: hA(0) ----
    {
        int s = tid & 3;
        float4 s0 = *(const float4*)&S.st[s * 8];
        float4 s1 = *(const float4*)&S.st[s * 8 + 4];
        float v = S.l0p[tid];
        v = fmaf(w0spR[0], s0.x, v); v = fmaf(w0spR[1], s0.y, v);
        v = fmaf(w0spR[2], s0.z, v); v = fmaf(w0spR[3], s0.w, v);
        v = fmaf(w0spR[4], s1.x, v); v = fmaf(w0spR[5], s1.y, v);
        v = fmaf(w0spR[6], s1.z, v); v = fmaf(w0spR[7], s1.w, v);
        S.hA[tid] = fmaxf(v, 0.f);
    }
    __syncthreads();

    // persistent stores in lane 0 of warps 0-3
    float sv[8];
    #pragma unroll
    for (int k = 0; k < 8; k++) sv[k] = (k == 1) ? 1.0f : 0.0f;

    for (int t = 0; t < STEPS; t++) {
        // ======== S1: layer1 partials (+ rain prefetch) ========
        if (t + 1 < STEPS && warp < 4 && lane == 0)
            rain_next = hyd[((t + 1) * BATCH + bsample) * 17 + 1];
        {
            u64 a01 = pack2(b1R, b1R), a23 = a01;
            const float* hp = &S.hA[q * 128];
            #pragma unroll
            for (int k = 0; k < 32; k++) {
                u64 wd = pack2(w1r[k], w1r[k]);
                ulonglong2 h = *(const ulonglong2*)&hp[k * 4];
                fma2(a01, h.x, wd); fma2(a23, h.y, wd);
            }
            ulonglong2 pv; pv.x = a01; pv.y = a23;
            *(ulonglong2*)&S.part1[q * 512 + j * 4] = pv;
        }
        __syncthreads();

        // ======== S2: combine1 -> hB ; stage x(t+1), LDG x(t+2) ========
        {
            float v = S.part1[tid]        + S.part1[512 + tid]
                    + S.part1[1024 + tid] + S.part1[1536 + tid];
            S.hB[tid] = fmaxf(v, 0.f);
        }
        if (warp >= 8 && warp < 12 && lane < 16) {
            S.xin[lane * 4 + (warp - 8)] = xreg;   // x(t+1)
            if (t + 2 < STEPS)
                xreg = hyd[((t + 2) * BATCH + xsample) * 17 + 1 + lane];
        }
        __syncthreads();

        // ======== S3: layer2 partials || l0x(t+1) ========
        if ((warp & 3) == 3) {
            int jj = q * 32 + lane;
            u64 a01 = pack2(b0R, b0R), a23 = a01;
            #pragma unroll
            for (int i = 0; i < 16; i++) {
                ulonglong2 h = *(const ulonglong2*)&S.xin[i * 4];
                u64 wd = pack2(w0tR[i], w0tR[i]);
                fma2(a01, h.x, wd); fma2(a23, h.y, wd);
            }
            ulonglong2 pv; pv.x = a01; pv.y = a23;
            *(ulonglong2*)&S.l0p[jj * 4] = pv;
        } else if (j < 89) {
            u64 a01 = pack2(bcR, bcR), a23 = a01;
            const float* hp = &S.hB[q * 128];
            #pragma unroll
            for (int k = 0; k < 32; k++) {
                u64 wd = pack2(wcr[k], wcr[k]);
                ulonglong2 h = *(const ulonglong2*)&hp[k * 4];
                fma2(a01, h.x, wd); fma2(a23, h.y, wd);
            }
            ulonglong2 pv; pv.x = a01; pv.y = a23;
            *(ulonglong2*)&S.part2[q * 384 + j * 4] = pv;
        }
        __syncthreads();

        // ======== S4: combine2; logits -> EXP, gates -> sigmoid ========
        if (tid < 356) {
            int jj = tid >> 2, s = tid & 3;
            float v = S.part2[tid]        + S.part2[384 + tid]
                    + S.part2[768 + tid]  + S.part2[1152 + tid];
            if (jj < 9) S.lgt[s * 16 + jj] = __expf(v);   // unnormalized
            else        S.outg[s * 80 + jj - 9] = fast_sigmoid(v);
        }
        __syncthreads();

        // ======== S5: epilogue (warps 0-3, lane 0 scalar; no MUFU) ========
        if (warp < 4 && lane == 0) {
            const int s = warp;
            float4 ea = *(const float4*)&S.lgt[s * 16];       // e0..e3
            float4 eb = *(const float4*)&S.lgt[s * 16 + 4];   // e4..e7
            float  e8 = S.lgt[s * 16 + 8];
            float ssum = (((ea.x + ea.y) + (ea.z + ea.w))
                        + ((eb.x + eb.y) + (eb.z + eb.w))) + e8;
            float r2 = __fdividef(rain_cur, ssum);
            sv[0] += ea.y * r2; sv[1] += ea.z * r2; sv[2] += ea.w * r2;
            sv[3] += eb.x * r2; sv[4] += eb.y * r2; sv[5] += eb.z * r2;
            sv[6] += eb.w * r2; sv[7] += e8   * r2;

            const float* bb = &S.outg[s * 80];
            #pragma unroll
            for (int d = 0; d < 8; d++) {
                float4 bv0 = *(const float4*)&bb[d * 8];
                float4 bv1 = *(const float4*)&bb[d * 8 + 4];
                float fb0 = bv0.x * sv[0], fb1 = bv0.y * sv[1];
                float fb2 = bv0.z * sv[2], fb3 = bv0.w * sv[3];
                float fb4 = bv1.x * sv[4], fb5 = bv1.y * sv[5];
                float fb6 = bv1.z * sv[6], fb7 = bv1.w * sv[7];
                float fsum = ((fb0 + fb1) + (fb2 + fb3))
                           + ((fb4 + fb5) + (fb6 + fb7));
                sv[0] -= fb0; sv[1] -= fb1; sv[2] -= fb2; sv[3] -= fb3;
                sv[4] -= fb4; sv[5] -= fb5; sv[6] -= fb6; sv[7] -= fb7;
                sv[d] += fsum;
            }
            {   // escape
                float4 ua = *(const float4*)&bb[64];
                float4 ub = *(const float4*)&bb[68];
                sv[0] -= ua.x * sv[0]; sv[1] -= ua.y * sv[1];
                sv[2] -= ua.z * sv[2]; sv[3] -= ua.w * sv[3];
                sv[4] -= ub.x * sv[4]; sv[5] -= ub.y * sv[5];
                sv[6] -= ub.z * sv[6]; sv[7] -= ub.w * sv[7];
            }
            {   // flow distn
                float4 f0 = *(const float4*)&bb[72];
                float4 f1 = *(const float4*)&bb[76];
                float fd0 = f0.x * sv[0], fd1 = f0.y * sv[1];
                float fd2 = f0.z * sv[2], fd3 = f0.w * sv[3];
                float fd4 = f1.x * sv[4], fd5 = f1.y * sv[5];
                float fd6 = f1.z * sv[6], fd7 = f1.w * sv[7];
                float flow = ((fd0 + fd1) + (fd2 + fd3))
                           + ((fd4 + fd5) + (fd6 + fd7));
                sv[0] -= fd0; sv[1] -= fd1; sv[2] -= fd2; sv[3] -= fd3;
                sv[4] -= fd4; sv[5] -= fd5; sv[6] -= fd6; sv[7] -= fd7;
                out[t * BATCH + bsample] = flow;
                if (t == 0)
                    sv[2] = S.bflow_s[s] / fmaxf(f0.z, 1e-5f);   // b_flow[SLOW]
            }
            *(float4*)&S.st[s * 8]     = make_float4(sv[0], sv[1], sv[2], sv[3]);
            *(float4*)&S.st[s * 8 + 4] = make_float4(sv[4], sv[5], sv[6], sv[7]);
            rain_cur = rain_next;
        }
        __syncthreads();

        // ======== S6: hA(t+1) finish (512 thr) ========
        {
            int s = tid & 3;
            float4 s0 = *(const float4*)&S.st[s * 8];
            float4 s1 = *(const float4*)&S.st[s * 8 + 4];
            float v = S.l0p[tid];
            v = fmaf(w0spR[0], s0.x, v); v = fmaf(w0spR[1], s0.y, v);
            v = fmaf(w0spR[2], s0.z, v); v = fmaf(w0spR[3], s0.w, v);
            v = fmaf(w0spR[4], s1.x, v); v = fmaf(w0spR[5], s1.y, v);
            v = fmaf(w0spR[6], s1.z, v); v = fmaf(w0spR[7], s1.w, v);
            S.hA[tid] = fmaxf(v, 0.f);
        }
        __syncthreads();
    }
}

// ---------------------------------------------------------------------------
// Harness entry.  Inputs: hyd_input, W0, b0, W1, b1, W_in, b_in, W_out, b_out
// ---------------------------------------------------------------------------
extern "C" void kernel_launch(void* const* d_in, const int* in_sizes, int n_in,
                              void* d_out, int out_size) {
    const float* hyd = (const float*)d_in[0];
    const float* W0  = (const float*)d_in[1];
    const float* b0  = (const float*)d_in[2];
    const float* W1  = (const float*)d_in[3];
    const float* b1  = (const float*)d_in[4];
    const float* Wi  = (const float*)d_in[5];
    const float* bi  = (const float*)d_in[6];
    const float* Wo  = (const float*)d_in[7];
    const float* bo  = (const float*)d_in[8];
    float* out = (float*)d_out;

    baseflow_kernel<<<BATCH, 1024>>>(hyd);
    hyd_kernel<<<NBLK, THREADS>>>(hyd, W0, b0, W1, b1, Wi, bi, Wo, bo, out);
}